// round 15
// baseline (speedup 1.0000x reference)
#include <cuda_runtime.h>
#include <cuda_bf16.h>

#define Bb 256
#define Tt 512
#define Ff 128
#define Uu 1024
#define N4 4096

typedef __nv_bfloat16 bf;

// ---------------- scratch (static device globals; no allocation) -------------
__device__ bf g_h0h[Bb * Uu]; __device__ bf g_h0l[Bb * Uu];
__device__ bf g_h1h[Bb * Uu]; __device__ bf g_h1l[Bb * Uu];
__device__ bf g_hsh[(size_t)Tt * Bb * Uu]; __device__ bf g_hsl[(size_t)Tt * Bb * Uu];
__device__ bf g_t1h[(size_t)Tt * Bb * Uu]; __device__ bf g_t1l[(size_t)Tt * Bb * Uu];
__device__ bf g_xh[(size_t)Bb * Tt * Ff];  __device__ bf g_xl[(size_t)Bb * Tt * Ff];
// weights transposed to [n][k] and split hi/lo
__device__ bf g_whTh[(size_t)N4 * Uu]; __device__ bf g_whTl[(size_t)N4 * Uu];
__device__ bf g_wdTh[(size_t)N4 * Uu]; __device__ bf g_wdTl[(size_t)N4 * Uu];
__device__ bf g_wxTh[(size_t)N4 * Ff]; __device__ bf g_wxTl[(size_t)N4 * Ff];
__device__ bf g_d1Th[(size_t)Uu * Uu]; __device__ bf g_d1Tl[(size_t)Uu * Uu];
__device__ bf g_d2Th[(size_t)Ff * Uu]; __device__ bf g_d2Tl[(size_t)Ff * Uu];
__device__ unsigned int g_bar;

// ---------------- helpers ----------------------------------------------------
__device__ __forceinline__ void split_bf(float v, bf& hi, bf& lo) {
    hi = __float2bfloat16_rn(v);
    lo = __float2bfloat16_rn(v - __bfloat162float(hi));
}
__device__ __forceinline__ void mma16(float c[4], const unsigned int a[4],
                                      const unsigned int b[2]) {
    asm volatile(
        "mma.sync.aligned.m16n8k16.row.col.f32.bf16.bf16.f32 "
        "{%0,%1,%2,%3}, {%4,%5,%6,%7}, {%8,%9}, {%0,%1,%2,%3};"
        : "+f"(c[0]), "+f"(c[1]), "+f"(c[2]), "+f"(c[3])
        : "r"(a[0]), "r"(a[1]), "r"(a[2]), "r"(a[3]), "r"(b[0]), "r"(b[1]));
}
__device__ __forceinline__ void ldm4(unsigned int r[4], unsigned int addr) {
    asm volatile("ldmatrix.sync.aligned.m8n8.x4.shared.b16 {%0,%1,%2,%3}, [%4];"
                 : "=r"(r[0]), "=r"(r[1]), "=r"(r[2]), "=r"(r[3]) : "r"(addr));
}
__device__ __forceinline__ float sigmoidf_(float x) {
    return 1.f / (1.f + __expf(-x));
}
__device__ __forceinline__ float tanhfast(float x) {
    float t = __expf(2.f * x);
    return 1.f - __fdividef(2.f, t + 1.f);
}
__device__ __forceinline__ void cpa16(unsigned int sa, const void* g) {
    // cg: bypass L1 — required: persistent kernel, h re-read across steps.
    asm volatile("cp.async.cg.shared.global [%0], [%1], 16;" :: "r"(sa), "l"(g));
}
#define COMMIT() asm volatile("cp.async.commit_group;")

// ---------------- prep: split to bf16 hi/lo, transpose weights ---------------
__global__ void __launch_bounds__(256) prep_kernel(
        const float* __restrict__ x,
        const float* __restrict__ ewx, const float* __restrict__ ewh,
        const float* __restrict__ dwx, const float* __restrict__ dwh,
        const float* __restrict__ d1w, const float* __restrict__ d2w) {
    int i = blockIdx.x * blockDim.x + threadIdx.x;
    if (i == 0) g_bar = 0u;
    if (i < Bb * Tt * Ff) split_bf(x[i], g_xh[i], g_xl[i]);
    if (i < N4 * Uu) {
        int k = i >> 12, n = i & 4095;
        size_t o = (size_t)n * Uu + k;
        split_bf(ewh[i],          g_whTh[o], g_whTl[o]);
        split_bf(dwx[i] + dwh[i], g_wdTh[o], g_wdTl[o]);
    }
    if (i < N4 * Ff) {
        int k = i >> 12, n = i & 4095;
        size_t o = (size_t)n * Ff + k;
        split_bf(ewx[i], g_wxTh[o], g_wxTl[o]);
    }
    if (i < Uu * Uu) {
        int k = i >> 10, n = i & 1023;
        size_t o = (size_t)n * Uu + k;
        split_bf(d1w[i], g_d1Th[o], g_d1Tl[o]);
    }
    if (i < Uu * Ff) {
        int k = i >> 7, n = i & 127;
        size_t o = (size_t)n * Uu + k;
        split_bf(d2w[i], g_d2Th[o], g_d2Tl[o]);
    }
    if (i < Bb * Uu) {
        g_h0h[i] = __float2bfloat16(0.f); g_h0l[i] = __float2bfloat16(0.f);
    }
}

// ---------------- persistent recurrence kernel --------------------------------
// 256 CTAs (64 u-tiles x 4 m-tiles), 256 threads (8 warps 2m x 4n), 2 CTAs/SM.
// CTA tile 64 rows x 64 cols (16 u x 4 gates, col=(wn*16)+(nb*8)+(2q)+(e),
// gate=(nb<<1)|e, u=u0+wn*4+q). K=64 chunks, 3-stage ring, bf16x3.
// Stage (row stride 144B): Ah@0(9216) Al@9216 Bh@18432 Bl@27648; STG=36864.
#define STG_SZ 36864u
#define L_TOTAL (3u * STG_SZ)   // 110592 B per CTA -> 2 CTAs/SM fits 228KB

__device__ __forceinline__ void fill_A(unsigned int sb, int st,
        const bf* Ah, const bf* Al, size_t lda, int tid) {
    unsigned int base = sb + st * STG_SZ;
#pragma unroll
    for (int s = 0; s < 2; s++) {
        int idx = tid + s * 256;
        int row = idx >> 3, seg = idx & 7;
        unsigned int sa = base + row * 144 + seg * 16;
        cpa16(sa, Ah + (size_t)row * lda + seg * 8);
        cpa16(sa + 9216u, Al + (size_t)row * lda + seg * 8);
    }
}
__device__ __forceinline__ void fill_B(unsigned int sb, int st,
        const bf* Bh, const bf* Bl, size_t ldb, int u0, int tid) {
    unsigned int base = sb + st * STG_SZ + 18432u;
#pragma unroll
    for (int s = 0; s < 2; s++) {
        int idx = tid + s * 256;
        int nn = idx >> 3, seg = idx & 7;
        int wn_ = nn >> 4, rem = nn & 15;
        int nb = rem >> 3, qq = (rem >> 1) & 3, e = rem & 1;
        int gate = (nb << 1) | e;
        size_t grow = (size_t)((gate << 10) + u0 + wn_ * 4 + qq) * ldb;
        unsigned int sa = base + nn * 144 + seg * 16;
        cpa16(sa, Bh + grow + seg * 8);
        cpa16(sa + 9216u, Bl + grow + seg * 8);
    }
}

__global__ void __launch_bounds__(256, 2) lstm_persist(const float* __restrict__ eb,
                                                       const float* __restrict__ db) {
    extern __shared__ char smraw[];
    const unsigned int sb = (unsigned int)__cvta_generic_to_shared(smraw);
    const int u0 = blockIdx.x * 16;          // 64 u-tiles of 16
    const int m0 = blockIdx.y * 64;          // 4 m-tiles of 64
    const int tid = threadIdx.x, lane = tid & 31, wid = tid >> 5;
    const int wm = wid >> 2, wn = wid & 3, r = lane >> 2, q = lane & 3;

    // ldmatrix per-lane offsets (row stride 144B)
    const int arow = wm * 32 + (lane & 7) + ((lane >> 3) & 1) * 8;
    const unsigned int aoff = (unsigned int)(arow * 144 + (lane >> 4) * 16);
    const int brow = wn * 16 + (lane & 7) + ((lane >> 4) & 1) * 8;
    const unsigned int boff = (unsigned int)(brow * 144 + ((lane >> 3) & 1) * 16);

    const int my_u = u0 + wn * 4 + q;
    float b0 = 0.f, b1 = 0.f, b2 = 0.f, b3 = 0.f;

    float c_reg[4];                          // (mb, rh)
#pragma unroll
    for (int s = 0; s < 4; s++) c_reg[s] = 0.f;

    // prefill for step tn: enc = full x0(st0), x1(st1), B2(st2: Wh k0);
    //                      dec = B0,B1,B2 (Wd k 0,64,128)
    auto prefill = [&](int tn) {
        if (tn >= 2 * Tt) return;
        if (tn < Tt) {
            size_t xoff = (size_t)m0 * (Tt * Ff) + (size_t)tn * Ff;
#pragma unroll
            for (int p = 0; p < 2; p++) {
                fill_A(sb, p, g_xh + xoff + p * 64, g_xl + xoff + p * 64,
                       (size_t)Tt * Ff, tid);
                fill_B(sb, p, g_wxTh + p * 64, g_wxTl + p * 64, (size_t)Ff, u0, tid);
                COMMIT();
            }
            fill_B(sb, 2, g_whTh, g_whTl, (size_t)Uu, u0, tid);
            COMMIT();
        } else {
#pragma unroll
            for (int p = 0; p < 3; p++) {
                fill_B(sb, p, g_wdTh + p * 64, g_wdTl + p * 64, (size_t)Uu, u0, tid);
                COMMIT();
            }
        }
    };

    prefill(0);

    for (int t = 0; t < 2 * Tt; t++) {
        const int is_dec = (t >= Tt);
        const bf *hih, *hil; bf *hoh, *hol;
        const bf *Wh, *Wl;
        int NC, ts;
        if (is_dec) {
            ts = t - Tt;
            Wh = g_wdTh; Wl = g_wdTl; NC = 16;
            if (ts == 0) { hih = g_h0h; hil = g_h0l; }
            else { hih = g_hsh + (size_t)(ts - 1) * Bb * Uu;
                   hil = g_hsl + (size_t)(ts - 1) * Bb * Uu; }
            hoh = g_hsh + (size_t)ts * Bb * Uu;
            hol = g_hsl + (size_t)ts * Bb * Uu;
        } else {
            ts = t;
            Wh = g_whTh; Wl = g_whTl; NC = 18;   // 2 x + 16 h chunks
            if (ts & 1) { hih = g_h1h; hil = g_h1l; hoh = g_h0h; hol = g_h0l; }
            else        { hih = g_h0h; hil = g_h0l; hoh = g_h1h; hol = g_h1l; }
        }
        if (t == 0 || t == Tt) {
            const float* bs = is_dec ? db : eb;
            b0 = bs[my_u]; b1 = bs[my_u + 1024];
            b2 = bs[my_u + 2048]; b3 = bs[my_u + 3072];
        }

        float acc[2][2][4];
#pragma unroll
        for (int a = 0; a < 2; a++)
#pragma unroll
            for (int b = 0; b < 2; b++)
#pragma unroll
                for (int e = 0; e < 4; e++) acc[a][b][e] = 0.f;

        auto mma_chunk = [&](int c) {
            const unsigned int base = sb + (c % 3) * STG_SZ;
            const unsigned int aH = base + aoff;
            const unsigned int aL = base + 9216u + aoff;
            const unsigned int bH = base + 18432u + boff;
            const unsigned int bL = base + 27648u + boff;
#pragma unroll
            for (int kh = 0; kh < 4; kh++) {
                const unsigned int kb = kh * 32;
                unsigned int ah[2][4], al[2][4], bh[2][2], bl[2][2];
#pragma unroll
                for (int mb = 0; mb < 2; mb++) {
                    ldm4(ah[mb], aH + mb * 2304u + kb);
                    ldm4(al[mb], aL + mb * 2304u + kb);
                }
                {
                    unsigned int tmp[4];
                    ldm4(tmp, bH + kb);
                    bh[0][0] = tmp[0]; bh[0][1] = tmp[1];
                    bh[1][0] = tmp[2]; bh[1][1] = tmp[3];
                    ldm4(tmp, bL + kb);
                    bl[0][0] = tmp[0]; bl[0][1] = tmp[1];
                    bl[1][0] = tmp[2]; bl[1][1] = tmp[3];
                }
                // per-accumulator order hh,lh,hl — numerics unchanged
#pragma unroll
                for (int nb = 0; nb < 2; nb++) {
                    mma16(acc[0][nb], ah[0], bh[nb]);
                    mma16(acc[1][nb], ah[1], bh[nb]);
                }
#pragma unroll
                for (int nb = 0; nb < 2; nb++) {
                    mma16(acc[0][nb], al[0], bh[nb]);
                    mma16(acc[1][nb], al[1], bh[nb]);
                }
#pragma unroll
                for (int nb = 0; nb < 2; nb++) {
                    mma16(acc[0][nb], ah[0], bl[nb]);
                    mma16(acc[1][nb], ah[1], bl[nb]);
                }
            }
        };

        auto fill_full = [&](int c) {          // h chunk: A + B, one commit
            int hc = is_dec ? c : (c - 2);
            fill_A(sb, c % 3, hih + (size_t)m0 * Uu + hc * 64,
                   hil + (size_t)m0 * Uu + hc * 64, (size_t)Uu, tid);
            fill_B(sb, c % 3, Wh + hc * 64, Wl + hc * 64, (size_t)Uu, u0, tid);
            COMMIT();
        };

        int cstart;
        if (!is_dec) {
            // x chunks computed BEFORE the grid-barrier wait (static data)
            asm volatile("cp.async.wait_group 2;");
            __syncthreads();
            mma_chunk(0);
            asm volatile("cp.async.wait_group 1;");
            __syncthreads();
            mma_chunk(1);
            if (tid == 0) {
                unsigned int target = 256u * (unsigned int)t;
                while (*((volatile unsigned int*)&g_bar) < target) {}
            }
            __syncthreads();
            // stage2 has B2 prefilled; add A2, then full chunk 3
            fill_A(sb, 2, hih + (size_t)m0 * Uu, hil + (size_t)m0 * Uu,
                   (size_t)Uu, tid);
            COMMIT();                          // queue: {B2, A2}
            fill_full(3);                      // {B2, A2, F3}
            cstart = 2;
            // c=2: wait 1 -> B2,A2 done. then fill c+2 each iter.
        } else {
            if (tid == 0) {
                unsigned int target = 256u * (unsigned int)t;
                while (*((volatile unsigned int*)&g_bar) < target) {}
            }
            __syncthreads();
            // B0,B1,B2 prefilled; add the h-dependent A halves
#pragma unroll
            for (int p = 0; p < 3; p++) {
                fill_A(sb, p, hih + (size_t)m0 * Uu + p * 64,
                       hil + (size_t)m0 * Uu + p * 64, (size_t)Uu, tid);
                COMMIT();
            }                                  // queue: {B0,B1,B2,A0,A1,A2}
            cstart = 0;
        }

        for (int c = cstart; c < NC; c++) {
            if (is_dec && c == 0) asm volatile("cp.async.wait_group 2;");
            else                  asm volatile("cp.async.wait_group 1;");
            __syncthreads();
            if (is_dec && c == 0) {
                // no fill/commit this iter (keeps queue {A1,A2})
            } else if (c + 2 < NC) {
                fill_full(c + 2);
            } else {
                COMMIT();                      // empty: keep FIFO accounting
            }
            mma_chunk(c);
        }
        asm volatile("cp.async.wait_group 0;");
        __syncthreads();                       // all mma done

        // cell math from accumulators; h staged in stage-2 A region (free now)
        bf* hsth = (bf*)(smraw + 2 * STG_SZ);          // [64][16] hi (2 KB)
        bf* hstl = (bf*)(smraw + 2 * STG_SZ + 2048);   // [64][16] lo (2 KB)
#pragma unroll
        for (int mb = 0; mb < 2; mb++)
#pragma unroll
            for (int rh = 0; rh < 2; rh++) {
                float zi = acc[mb][0][rh * 2    ] + b0;
                float zf = acc[mb][0][rh * 2 + 1] + b1;
                float zg = acc[mb][1][rh * 2    ] + b2;
                float zo = acc[mb][1][rh * 2 + 1] + b3;
                float ig = sigmoidf_(zi);
                float fg = sigmoidf_(zf);
                float gg = tanhfast(zg);
                float og = sigmoidf_(zo);
                int ci = mb * 2 + rh;
                float cn = fg * c_reg[ci] + ig * gg;
                c_reg[ci] = cn;
                float h = og * tanhfast(cn);
                int row = wm * 32 + mb * 16 + r + rh * 8;
                int uc = wn * 4 + q;
                split_bf(h, hsth[row * 16 + uc], hstl[row * 16 + uc]);
            }
        __syncthreads();
        {   // cooperative coalesced h store: 64 rows x 16 u, hi+lo (2KB each)
            if (tid < 128) {
                int row = tid >> 1, sg = tid & 1;
                *(uint4*)(hoh + (size_t)(m0 + row) * Uu + u0 + sg * 8) =
                    *(const uint4*)(smraw + 2 * STG_SZ + row * 32 + sg * 16);
            } else {
                int t2 = tid - 128;
                int row = t2 >> 1, sg = t2 & 1;
                *(uint4*)(hol + (size_t)(m0 + row) * Uu + u0 + sg * 8) =
                    *(const uint4*)(smraw + 2 * STG_SZ + 2048 + row * 32 + sg * 16);
            }
        }
        __syncthreads();                       // stores issued by all threads
        if (tid == 0) {
            __threadfence();
            atomicAdd(&g_bar, 1u);             // arrive; wait deferred
        }
        prefill(t + 1);                        // h-independent fills overlap skew
    }
}

// ---------------- dense epilogue GEMMs (bf16x3, ldmatrix + cp.async ring) -----
#define D_AH 0u
#define D_AL 15360u
#define D_BH 30720u
#define D_BL 46080u
#define D_TOTAL 61440u

template <int SRC>
__global__ void __launch_bounds__(256) dense_kernel(const float* __restrict__ bias,
                                                    float* __restrict__ outp) {
    const bf* Agh = (SRC == 0) ? g_hsh : g_t1h;
    const bf* Agl = (SRC == 0) ? g_hsl : g_t1l;
    const bf* Bgh = (SRC == 0) ? g_d1Th : g_d2Th;
    const bf* Bgl = (SRC == 0) ? g_d1Tl : g_d2Tl;
    extern __shared__ char smraw[];
    const unsigned int sb = (unsigned int)__cvta_generic_to_shared(smraw);
    const int n0 = blockIdx.x * 64;
    const int m0 = blockIdx.y * 64;
    const int tid = threadIdx.x, lane = tid & 31, wid = tid >> 5;
    const int wm = wid >> 2, wn = wid & 3, r = lane >> 2, q = lane & 3;

    const int arow = wm * 32 + (lane & 7) + ((lane >> 3) & 1) * 8;
    const unsigned int aoff = (unsigned int)(arow * 80 + (lane >> 4) * 16);
    const int brow = wn * 16 + (lane & 7) + ((lane >> 4) & 1) * 8;
    const unsigned int boff = (unsigned int)(brow * 80 + ((lane >> 3) & 1) * 16);

    float acc[2][2][4];
#pragma unroll
    for (int a = 0; a < 2; a++)
#pragma unroll
        for (int b = 0; b < 2; b++)
#pragma unroll
            for (int e = 0; e < 4; e++) acc[a][b][e] = 0.f;

    const int frow = tid >> 2, fseg = (tid & 3) * 8;
    auto fill = [&](int st, int c) {
        unsigned int sa = sb + st * 5120u + (unsigned int)(frow * 80 + fseg * 2);
        size_t ga = (size_t)(m0 + frow) * 1024 + c * 32 + fseg;
        size_t gb = (size_t)(n0 + frow) * 1024 + c * 32 + fseg;
        cpa16(sa + D_AH, Agh + ga);
        cpa16(sa + D_AL, Agl + ga);
        cpa16(sa + D_BH, Bgh + gb);
        cpa16(sa + D_BL, Bgl + gb);
        COMMIT();
    };

    fill(0, 0); fill(1, 1);
    for (int c = 0; c < 32; c++) {
        asm volatile("cp.async.wait_group 1;");
        __syncthreads();
        if (c + 2 < 32) fill((c + 2) % 3, c + 2);
        else COMMIT();

        const int st = c % 3;
        const unsigned int aH = sb + st * 5120u + D_AH + aoff;
        const unsigned int aL = sb + st * 5120u + D_AL + aoff;
        const unsigned int bH = sb + st * 5120u + D_BH + boff;
        const unsigned int bL = sb + st * 5120u + D_BL + boff;

        unsigned int ah[2][2][4], al[2][2][4], bh[2][2][2], bl[2][2][2];
        auto load_frags = [&](int buf, int kb) {
#pragma unroll
            for (int mb = 0; mb < 2; mb++) {
                ldm4(ah[buf][mb], aH + mb * 1280u + kb * 2);
                ldm4(al[buf][mb], aL + mb * 1280u + kb * 2);
            }
            unsigned int tmp[4];
            ldm4(tmp, bH + kb * 2);
            bh[buf][0][0] = tmp[0]; bh[buf][0][1] = tmp[1];
            bh[buf][1][0] = tmp[2]; bh[buf][1][1] = tmp[3];
            ldm4(tmp, bL + kb * 2);
            bl[buf][0][0] = tmp[0]; bl[buf][0][1] = tmp[1];
            bl[buf][1][0] = tmp[2]; bl[buf][1][1] = tmp[3];
        };
        load_frags(0, 0);
#pragma unroll
        for (int kh = 0; kh < 2; kh++) {
            if (kh == 0) load_frags(1, 16);
#pragma unroll
            for (int nb = 0; nb < 2; nb++) {
                mma16(acc[0][nb], ah[kh][0], bh[kh][nb]);
                mma16(acc[1][nb], ah[kh][1], bh[kh][nb]);
            }
#pragma unroll
            for (int nb = 0; nb < 2; nb++) {
                mma16(acc[0][nb], al[kh][0], bh[kh][nb]);
                mma16(acc[1][nb], al[kh][1], bh[kh][nb]);
            }
#pragma unroll
            for (int nb = 0; nb < 2; nb++) {
                mma16(acc[0][nb], ah[kh][0], bl[kh][nb]);
                mma16(acc[1][nb], ah[kh][1], bl[kh][nb]);
            }
        }
        __syncthreads();
    }
    asm volatile("cp.async.wait_group 0;");

#pragma unroll
    for (int mb = 0; mb < 2; mb++)
#pragma unroll
        for (int nb = 0; nb < 2; nb++) {
            int rwb = m0 + wm * 32 + mb * 16 + r;
            int cwb = n0 + wn * 16 + nb * 8 + 2 * q;
#pragma unroll
            for (int e = 0; e < 4; e++) {
                int rr = rwb + (e >> 1) * 8;
                int cc = cwb + (e & 1);
                float v = acc[mb][nb][e] + bias[cc];
                if (SRC == 0) {
                    v = fmaxf(v, 0.f);
                    size_t o = (size_t)rr * 1024 + cc;
                    split_bf(v, g_t1h[o], g_t1l[o]);
                } else {
                    int tt = rr >> 8, bb = rr & 255;   // row = t*256 + b
                    outp[((size_t)bb * Tt + tt) * Ff + cc] = v;
                }
            }
        }
}

// ---------------- launch ------------------------------------------------------
extern "C" void kernel_launch(void* const* d_in, const int* in_sizes, int n_in,
                              void* d_out, int out_size) {
    const float* x   = (const float*)d_in[0];
    const float* ewx = (const float*)d_in[1];
    const float* ewh = (const float*)d_in[2];
    const float* eb  = (const float*)d_in[3];
    const float* dwx = (const float*)d_in[4];
    const float* dwh = (const float*)d_in[5];
    const float* db  = (const float*)d_in[6];
    const float* d1w = (const float*)d_in[7];
    const float* d1b = (const float*)d_in[8];
    const float* d2w = (const float*)d_in[9];
    const float* d2b = (const float*)d_in[10];
    float* out = (float*)d_out;

    cudaFuncSetAttribute(lstm_persist, cudaFuncAttributeMaxDynamicSharedMemorySize,
                         (int)L_TOTAL);
    cudaFuncSetAttribute(dense_kernel<0>, cudaFuncAttributeMaxDynamicSharedMemorySize,
                         (int)D_TOTAL);
    cudaFuncSetAttribute(dense_kernel<1>, cudaFuncAttributeMaxDynamicSharedMemorySize,
                         (int)D_TOTAL);

    prep_kernel<<<(Bb * Tt * Ff + 255) / 256, 256>>>(x, ewx, ewh, dwx, dwh, d1w, d2w);

    dim3 sgrid(Uu / 16, Bb / 64);   // 256 CTAs: 2 per SM, single wave
    lstm_persist<<<sgrid, 256, L_TOTAL>>>(eb, db);

    dense_kernel<0><<<dim3(1024 / 64, (Tt * Bb) / 64), 256, D_TOTAL>>>(d1b, nullptr);
    dense_kernel<1><<<dim3(128 / 64, (Tt * Bb) / 64), 256, D_TOTAL>>>(d2b, out);
}